// round 5
// baseline (speedup 1.0000x reference)
#include <cuda_runtime.h>
#include <cstdint>
#include <math.h>

// SimRel via bf16-split mma.sync (HMMA). R5: 16 warps (512 thr), warp-pair
// N-split (each warp: 16 rows x 32 classes), register prefetch of next tile's
// X rows overlapped with MMA phase. D = Xhi*Ahi + Xhi*Alo + Xlo*Ahi (fp32 acc).
// B=262144, D=256, C=64.

#define THREADS 512
#define SPITCH  264                 // bf16 elems per smem row (256 + 8 pad)
#define SROW    528                 // bytes

// ---- smem layout (bytes) ----
#define S_AHI   0                   // [64 x 264] bf16    33792
#define S_ALO   33792               //                    33792
#define S_XHI   67584               // [128 x 264] bf16   67584
#define S_XLO   135168              //                    67584
#define S_XINV  202752              // [128] f32            512
#define S_CNI   203264              // [64] f32             256
#define S_INF   203520              // [64] int             256
#define S_TOTAL 203776

__device__ __forceinline__ void sts64(uint32_t a, uint32_t x, uint32_t y) {
    asm volatile("st.shared.v2.b32 [%0], {%1,%2};" :: "r"(a), "r"(x), "r"(y));
}
__device__ __forceinline__ void ldsm4(uint32_t a, uint32_t& r0, uint32_t& r1,
                                      uint32_t& r2, uint32_t& r3) {
    asm volatile("ldmatrix.sync.aligned.m8n8.x4.shared.b16 {%0,%1,%2,%3}, [%4];"
                 : "=r"(r0), "=r"(r1), "=r"(r2), "=r"(r3) : "r"(a));
}
__device__ __forceinline__ void mma16816(float* c, uint32_t a0, uint32_t a1,
                                         uint32_t a2, uint32_t a3,
                                         uint32_t b0, uint32_t b1) {
    asm volatile("mma.sync.aligned.m16n8k16.row.col.f32.bf16.bf16.f32 "
                 "{%0,%1,%2,%3}, {%4,%5,%6,%7}, {%8,%9}, {%0,%1,%2,%3};"
                 : "+f"(c[0]), "+f"(c[1]), "+f"(c[2]), "+f"(c[3])
                 : "r"(a0), "r"(a1), "r"(a2), "r"(a3), "r"(b0), "r"(b1));
}

// fp32 float4 -> hi (truncated bf16x2 pair) + lo (rn bf16x2 of residual)
__device__ __forceinline__ void cvt_split(float4 v, uint32_t& h0, uint32_t& h1,
                                          uint32_t& l0, uint32_t& l1) {
    uint32_t xb = __float_as_uint(v.x), yb = __float_as_uint(v.y);
    uint32_t zb = __float_as_uint(v.z), wb = __float_as_uint(v.w);
    h0 = __byte_perm(xb, yb, 0x7632);
    h1 = __byte_perm(zb, wb, 0x7632);
    float lx = v.x - __uint_as_float(xb & 0xFFFF0000u);
    float ly = v.y - __uint_as_float(yb & 0xFFFF0000u);
    float lz = v.z - __uint_as_float(zb & 0xFFFF0000u);
    float lw = v.w - __uint_as_float(wb & 0xFFFF0000u);
    asm("cvt.rn.bf16x2.f32 %0, %1, %2;" : "=r"(l0) : "f"(ly), "f"(lx));
    asm("cvt.rn.bf16x2.f32 %0, %1, %2;" : "=r"(l1) : "f"(lw), "f"(lz));
}

__device__ __forceinline__ float sum8(float4 a, float4 b) {
    float s = a.x * a.x;
    s = fmaf(a.y, a.y, s); s = fmaf(a.z, a.z, s); s = fmaf(a.w, a.w, s);
    s = fmaf(b.x, b.x, s); s = fmaf(b.y, b.y, s);
    s = fmaf(b.z, b.z, s); s = fmaf(b.w, b.w, s);
    return s;
}

__global__ void __launch_bounds__(THREADS, 1)
SimRel_48335561949951_kernel(const float* __restrict__ X,
                             const float* __restrict__ A,
                             float* __restrict__ out,
                             int B, int ntiles) {
    extern __shared__ char smem[];
    const uint32_t sb = (uint32_t)__cvta_generic_to_shared(smem);
    float* xinv_s = (float*)(smem + S_XINV);
    float* cni_s  = (float*)(smem + S_CNI);
    int*   inf_s  = (int*)(smem + S_INF);

    const int tid = threadIdx.x, w = tid >> 5, l = tid & 31;
    const int p = w >> 1;           // pair id: owns rows p*16..p*16+15
    const int h = w & 1;            // N-half: classes h*32..h*32+31

    // ---- centroid conversion + norms (4 rows per warp, once) ----
    #pragma unroll
    for (int rr = 0; rr < 4; rr++) {
        int r = w * 4 + rr;
        const float4* pa = (const float4*)(A + (size_t)r * 256);
        float4 v0 = pa[l], v1 = pa[32 + l];
        uint32_t h0, h1, q0, q1;
        cvt_split(v0, h0, h1, q0, q1);
        sts64(sb + S_AHI + r * SROW + 8 * l, h0, h1);
        sts64(sb + S_ALO + r * SROW + 8 * l, q0, q1);
        cvt_split(v1, h0, h1, q0, q1);
        sts64(sb + S_AHI + r * SROW + 256 + 8 * l, h0, h1);
        sts64(sb + S_ALO + r * SROW + 256 + 8 * l, q0, q1);
        float ss = sum8(v0, v1);
        int bad = (fabsf(v0.x) == INFINITY) | (fabsf(v0.y) == INFINITY) |
                  (fabsf(v0.z) == INFINITY) | (fabsf(v0.w) == INFINITY) |
                  (fabsf(v1.x) == INFINITY) | (fabsf(v1.y) == INFINITY) |
                  (fabsf(v1.z) == INFINITY) | (fabsf(v1.w) == INFINITY);
        #pragma unroll
        for (int o = 16; o; o >>= 1) ss += __shfl_xor_sync(0xffffffffu, ss, o);
        unsigned m = __ballot_sync(0xffffffffu, bad);
        if (l == 0) { cni_s[r] = rsqrtf(ss); inf_s[r] = (m != 0); }
    }
    __syncthreads();

    // ---- per-lane ldmatrix address components ----
    const int t8 = l >> 3;
    const uint32_t frag_off = (uint32_t)(((t8 & 1) * 8 + (l & 7)) * SROW + (t8 >> 1) * 16);
    const uint32_t xfh = sb + S_XHI + (uint32_t)(p * 16) * SROW + frag_off;
    const uint32_t xfl = sb + S_XLO + (uint32_t)(p * 16) * SROW + frag_off;
    const uint32_t afh = sb + S_AHI + (uint32_t)(h * 32) * SROW + frag_off;
    const uint32_t afl = sb + S_ALO + (uint32_t)(h * 32) * SROW + frag_off;

    const int rbase = p * 16 + h * 8;                    // this warp's 8 load rows
    const uint32_t xsh = sb + S_XHI + (uint32_t)rbase * SROW;
    const uint32_t xsl = sb + S_XLO + (uint32_t)rbase * SROW;

    const int qr = l >> 2, qc = (l & 3) * 2;

    // ---- prologue: prefetch first tile's 8 rows into registers ----
    float4 va[8], vb[8];
    {
        long long tb = (long long)blockIdx.x * 128;
        #pragma unroll
        for (int rr = 0; rr < 8; rr++) {
            long long gr = tb + rbase + rr; if (gr >= B) gr = B - 1;
            const float4* px = (const float4*)(X + gr * 256);
            va[rr] = px[l];
            vb[rr] = px[32 + l];
        }
    }

    for (int tile = blockIdx.x; tile < ntiles; tile += gridDim.x) {
        const long long tb = (long long)tile * 128;

        // phase 1: convert prefetched rows -> bf16 hi/lo smem + row norms
        #pragma unroll
        for (int rr = 0; rr < 8; rr++) {
            uint32_t h0, h1, q0, q1;
            cvt_split(va[rr], h0, h1, q0, q1);
            sts64(xsh + rr * SROW + 8 * l, h0, h1);
            sts64(xsl + rr * SROW + 8 * l, q0, q1);
            cvt_split(vb[rr], h0, h1, q0, q1);
            sts64(xsh + rr * SROW + 256 + 8 * l, h0, h1);
            sts64(xsl + rr * SROW + 256 + 8 * l, q0, q1);
            float ss = sum8(va[rr], vb[rr]);
            #pragma unroll
            for (int o = 16; o; o >>= 1) ss += __shfl_xor_sync(0xffffffffu, ss, o);
            if (l == 0) xinv_s[rbase + rr] = rsqrtf(ss);
        }
        __syncthreads();

        // phase 2a: issue next tile's LDGs (covered by MMA below)
        int nt = tile + gridDim.x;
        if (nt < ntiles) {
            long long nb = (long long)nt * 128;
            #pragma unroll
            for (int rr = 0; rr < 8; rr++) {
                long long gr = nb + rbase + rr; if (gr >= B) gr = B - 1;
                const float4* px = (const float4*)(X + gr * 256);
                va[rr] = px[l];
                vb[rr] = px[32 + l];
            }
        }

        // phase 2b: 3 bf16-split passes x 16 k-steps, N=32 per warp
        float acc[4][4];
        #pragma unroll
        for (int nb2 = 0; nb2 < 4; nb2++)
            #pragma unroll
            for (int j = 0; j < 4; j++) acc[nb2][j] = 0.0f;

        #pragma unroll
        for (int pass = 0; pass < 3; pass++) {
            const uint32_t xf = (pass == 2) ? xfl : xfh;
            const uint32_t af = (pass == 1) ? afl : afh;
            #pragma unroll
            for (int s = 0; s < 16; s++) {
                uint32_t a0, a1, a2, a3;
                ldsm4(xf + s * 32, a0, a1, a2, a3);
                #pragma unroll
                for (int hb = 0; hb < 2; hb++) {
                    uint32_t b0, b1, b2, b3;
                    ldsm4(af + hb * (16 * SROW) + s * 32, b0, b1, b2, b3);
                    mma16816(acc[hb * 2 + 0], a0, a1, a2, a3, b0, b2);
                    mma16816(acc[hb * 2 + 1], a0, a1, a2, a3, b1, b3);
                }
            }
        }

        // phase 3: epilogue — scale + store (16 rows x 32 classes per warp)
        float xi0 = xinv_s[p * 16 + qr];
        float xi1 = xinv_s[p * 16 + 8 + qr];
        long long r0g = tb + p * 16 + qr;
        float* o0 = out + r0g * 64;
        float* o1 = o0 + 8 * 64;
        #pragma unroll
        for (int nb2 = 0; nb2 < 4; nb2++) {
            int c0 = h * 32 + nb2 * 8 + qc;
            float2 cn2 = *(const float2*)(cni_s + c0);
            int2   ff  = *(const int2*)(inf_s + c0);
            float2 s0, s1;
            s0.x = ff.x ? 1.0f : acc[nb2][0] * xi0 * cn2.x;
            s0.y = ff.y ? 1.0f : acc[nb2][1] * xi0 * cn2.y;
            s1.x = ff.x ? 1.0f : acc[nb2][2] * xi1 * cn2.x;
            s1.y = ff.y ? 1.0f : acc[nb2][3] * xi1 * cn2.y;
            if (r0g < B)     *(float2*)(o0 + c0) = s0;
            if (r0g + 8 < B) *(float2*)(o1 + c0) = s1;
        }
        __syncthreads();   // protect X smem + xinv (WAR) before next convert
    }
}

extern "C" void kernel_launch(void* const* d_in, const int* in_sizes, int n_in,
                              void* d_out, int out_size) {
    const float* X = (const float*)d_in[0];   // inputs [B, 256] fp32
    // d_in[1] = labels (unused)
    const float* A = (const float*)d_in[2];   // class_avgs [64, 256] fp32
    float* out = (float*)d_out;

    int B = in_sizes[0] / 256;
    int ntiles = (B + 127) / 128;

    int dev = 0, nsm = 148;
    cudaGetDevice(&dev);
    cudaDeviceGetAttribute(&nsm, cudaDevAttrMultiProcessorCount, dev);
    if (nsm > ntiles) nsm = ntiles;

    cudaFuncSetAttribute(SimRel_48335561949951_kernel,
                         cudaFuncAttributeMaxDynamicSharedMemorySize, S_TOTAL);

    SimRel_48335561949951_kernel<<<nsm, THREADS, S_TOTAL>>>(X, A, out, B, ntiles);
}

// round 6
// speedup vs baseline: 2.1528x; 2.1528x over previous
#include <cuda_runtime.h>
#include <cstdint>
#include <math.h>

// SimRel via bf16-split mma.sync (HMMA). R6: 256 thr / 8 warps as 4 autonomous
// warp-PAIRS. Tile M=64, double-buffered X smem, register prefetch of next
// tile covered by MMA, one named barrier per pair per tile (no __syncthreads
// in the loop). D = Xhi*Ahi + Xhi*Alo + Xlo*Ahi (fp32 acc).
// B=262144, D=256, C=64.

#define THREADS 256
#define SPITCH  264                 // bf16 elems per smem row (256 + 8 pad)
#define SROW    528                 // bytes

// ---- smem layout (bytes) ----
#define S_AHI   0                   // [64 x 264] bf16            33792
#define S_ALO   33792               //                            33792
#define S_X0    67584               // buf0: XHI[64x264]+XLO      67584
#define S_X1    135168              // buf1                       67584
#define S_XLOFF 33792               // XLO offset within an X buf
#define S_XINV  202752              // [2][64] f32                  512
#define S_CNI   203264              // [64] f32                     256
#define S_INF   203520              // [64] int                     256
#define S_TOTAL 203776

__device__ __forceinline__ void sts64(uint32_t a, uint32_t x, uint32_t y) {
    asm volatile("st.shared.v2.b32 [%0], {%1,%2};" :: "r"(a), "r"(x), "r"(y));
}
__device__ __forceinline__ void ldsm4(uint32_t a, uint32_t& r0, uint32_t& r1,
                                      uint32_t& r2, uint32_t& r3) {
    asm volatile("ldmatrix.sync.aligned.m8n8.x4.shared.b16 {%0,%1,%2,%3}, [%4];"
                 : "=r"(r0), "=r"(r1), "=r"(r2), "=r"(r3) : "r"(a));
}
__device__ __forceinline__ void mma16816(float* c, uint32_t a0, uint32_t a1,
                                         uint32_t a2, uint32_t a3,
                                         uint32_t b0, uint32_t b1) {
    asm volatile("mma.sync.aligned.m16n8k16.row.col.f32.bf16.bf16.f32 "
                 "{%0,%1,%2,%3}, {%4,%5,%6,%7}, {%8,%9}, {%0,%1,%2,%3};"
                 : "+f"(c[0]), "+f"(c[1]), "+f"(c[2]), "+f"(c[3])
                 : "r"(a0), "r"(a1), "r"(a2), "r"(a3), "r"(b0), "r"(b1));
}

// fp32 float4 -> hi (truncated bf16x2 pair) + lo (rn bf16x2 of residual)
__device__ __forceinline__ void cvt_split(float4 v, uint32_t& h0, uint32_t& h1,
                                          uint32_t& l0, uint32_t& l1) {
    uint32_t xb = __float_as_uint(v.x), yb = __float_as_uint(v.y);
    uint32_t zb = __float_as_uint(v.z), wb = __float_as_uint(v.w);
    h0 = __byte_perm(xb, yb, 0x7632);
    h1 = __byte_perm(zb, wb, 0x7632);
    float lx = v.x - __uint_as_float(xb & 0xFFFF0000u);
    float ly = v.y - __uint_as_float(yb & 0xFFFF0000u);
    float lz = v.z - __uint_as_float(zb & 0xFFFF0000u);
    float lw = v.w - __uint_as_float(wb & 0xFFFF0000u);
    asm("cvt.rn.bf16x2.f32 %0, %1, %2;" : "=r"(l0) : "f"(ly), "f"(lx));
    asm("cvt.rn.bf16x2.f32 %0, %1, %2;" : "=r"(l1) : "f"(lw), "f"(lz));
}

__device__ __forceinline__ float sum8(float4 a, float4 b) {
    float s = a.x * a.x;
    s = fmaf(a.y, a.y, s); s = fmaf(a.z, a.z, s); s = fmaf(a.w, a.w, s);
    s = fmaf(b.x, b.x, s); s = fmaf(b.y, b.y, s);
    s = fmaf(b.z, b.z, s); s = fmaf(b.w, b.w, s);
    return s;
}

__global__ void __launch_bounds__(THREADS, 1)
SimRel_48335561949951_kernel(const float* __restrict__ X,
                             const float* __restrict__ A,
                             float* __restrict__ out,
                             int B, int ntiles) {
    extern __shared__ char smem[];
    const uint32_t sb = (uint32_t)__cvta_generic_to_shared(smem);
    float* xinv_s = (float*)(smem + S_XINV);
    float* cni_s  = (float*)(smem + S_CNI);
    int*   inf_s  = (int*)(smem + S_INF);

    const int tid = threadIdx.x, w = tid >> 5, l = tid & 31;
    const int p = w >> 1;           // pair 0..3: owns tile rows p*16..p*16+15
    const int h = w & 1;            // N-half: classes h*32..h*32+31

    // ---- centroid conversion + norms (8 rows per warp, once) ----
    #pragma unroll
    for (int rr = 0; rr < 8; rr++) {
        int r = w * 8 + rr;
        const float4* pa = (const float4*)(A + (size_t)r * 256);
        float4 v0 = pa[l], v1 = pa[32 + l];
        uint32_t h0, h1, q0, q1;
        cvt_split(v0, h0, h1, q0, q1);
        sts64(sb + S_AHI + r * SROW + 8 * l, h0, h1);
        sts64(sb + S_ALO + r * SROW + 8 * l, q0, q1);
        cvt_split(v1, h0, h1, q0, q1);
        sts64(sb + S_AHI + r * SROW + 256 + 8 * l, h0, h1);
        sts64(sb + S_ALO + r * SROW + 256 + 8 * l, q0, q1);
        float ss = sum8(v0, v1);
        int bad = (fabsf(v0.x) == INFINITY) | (fabsf(v0.y) == INFINITY) |
                  (fabsf(v0.z) == INFINITY) | (fabsf(v0.w) == INFINITY) |
                  (fabsf(v1.x) == INFINITY) | (fabsf(v1.y) == INFINITY) |
                  (fabsf(v1.z) == INFINITY) | (fabsf(v1.w) == INFINITY);
        #pragma unroll
        for (int o = 16; o; o >>= 1) ss += __shfl_xor_sync(0xffffffffu, ss, o);
        unsigned m = __ballot_sync(0xffffffffu, bad);
        if (l == 0) { cni_s[r] = rsqrtf(ss); inf_s[r] = (m != 0); }
    }
    __syncthreads();

    // ---- per-lane ldmatrix fragment offsets ----
    const int t8 = l >> 3;
    const uint32_t frag_off = (uint32_t)(((t8 & 1) * 8 + (l & 7)) * SROW + (t8 >> 1) * 16);
    // a-frag: rows p*16.. within X buf (hi at +0, lo at +S_XLOFF)
    const uint32_t xfrag = (uint32_t)(p * 16) * SROW + frag_off;
    // b-frags: centroid rows h*32 + hb*16
    const uint32_t afh = sb + S_AHI + (uint32_t)(h * 32) * SROW + frag_off;
    const uint32_t afl = sb + S_ALO + (uint32_t)(h * 32) * SROW + frag_off;

    const int rbase = p * 16 + h * 8;          // 8 rows this warp loads/converts
    const int qr = l >> 2, qc = (l & 3) * 2;
    const int barid = p + 1;

    // ---- prologue: prefetch first tile's 8 rows into registers ----
    float4 va[8], vb[8];
    {
        long long tb = (long long)blockIdx.x * 64;
        #pragma unroll
        for (int rr = 0; rr < 8; rr++) {
            long long gr = tb + rbase + rr; if (gr >= B) gr = B - 1;
            const float4* px = (const float4*)(X + gr * 256);
            va[rr] = px[l];
            vb[rr] = px[32 + l];
        }
    }

    int dp = 0;
    for (int tile = blockIdx.x; tile < ntiles; tile += gridDim.x) {
        const long long tb = (long long)tile * 64;
        const uint32_t xbuf = sb + (dp ? S_X1 : S_X0);

        // phase 1: convert prefetched rows -> bf16 hi/lo smem + row norms
        {
            const uint32_t xsh = xbuf + (uint32_t)rbase * SROW;
            const uint32_t xsl = xsh + S_XLOFF;
            #pragma unroll
            for (int rr = 0; rr < 8; rr++) {
                uint32_t h0, h1, q0, q1;
                cvt_split(va[rr], h0, h1, q0, q1);
                sts64(xsh + rr * SROW + 8 * l, h0, h1);
                sts64(xsl + rr * SROW + 8 * l, q0, q1);
                cvt_split(vb[rr], h0, h1, q0, q1);
                sts64(xsh + rr * SROW + 256 + 8 * l, h0, h1);
                sts64(xsl + rr * SROW + 256 + 8 * l, q0, q1);
                float ss = sum8(va[rr], vb[rr]);
                #pragma unroll
                for (int o = 16; o; o >>= 1) ss += __shfl_xor_sync(0xffffffffu, ss, o);
                if (l == 0) xinv_s[dp * 64 + rbase + rr] = rsqrtf(ss);
            }
        }
        // pair barrier: both warps' X writes visible; partner done with MMA(t-1)
        asm volatile("bar.sync %0, %1;" :: "r"(barid), "r"(64) : "memory");

        // phase 2a: issue next tile's LDGs (latency covered by MMA below)
        int nt = tile + gridDim.x;
        if (nt < ntiles) {
            long long nb = (long long)nt * 64;
            #pragma unroll
            for (int rr = 0; rr < 8; rr++) {
                long long gr = nb + rbase + rr; if (gr >= B) gr = B - 1;
                const float4* px = (const float4*)(X + gr * 256);
                va[rr] = px[l];
                vb[rr] = px[32 + l];
            }
        }

        // phase 2b: 3 bf16-split passes x 16 k-steps; M=16, N=32 per warp
        float acc[4][4];
        #pragma unroll
        for (int nb2 = 0; nb2 < 4; nb2++)
            #pragma unroll
            for (int j = 0; j < 4; j++) acc[nb2][j] = 0.0f;

        #pragma unroll
        for (int pass = 0; pass < 3; pass++) {
            const uint32_t xf = xbuf + xfrag + (pass == 2 ? S_XLOFF : 0);
            const uint32_t af = (pass == 1) ? afl : afh;
            #pragma unroll
            for (int s = 0; s < 16; s++) {
                uint32_t a0, a1, a2, a3;
                ldsm4(xf + s * 32, a0, a1, a2, a3);
                #pragma unroll
                for (int hb = 0; hb < 2; hb++) {
                    uint32_t b0, b1, b2, b3;
                    ldsm4(af + hb * (16 * SROW) + s * 32, b0, b1, b2, b3);
                    mma16816(acc[hb * 2 + 0], a0, a1, a2, a3, b0, b2);
                    mma16816(acc[hb * 2 + 1], a0, a1, a2, a3, b1, b3);
                }
            }
        }

        // phase 3: epilogue — scale + store (16 rows x 32 classes per warp)
        float xi0 = xinv_s[dp * 64 + p * 16 + qr];
        float xi1 = xinv_s[dp * 64 + p * 16 + 8 + qr];
        long long r0g = tb + p * 16 + qr;
        float* o0 = out + r0g * 64;
        float* o1 = o0 + 8 * 64;
        #pragma unroll
        for (int nb2 = 0; nb2 < 4; nb2++) {
            int c0 = h * 32 + nb2 * 8 + qc;
            float2 cn2 = *(const float2*)(cni_s + c0);
            int2   ff  = *(const int2*)(inf_s + c0);
            float2 s0, s1;
            s0.x = ff.x ? 1.0f : acc[nb2][0] * xi0 * cn2.x;
            s0.y = ff.y ? 1.0f : acc[nb2][1] * xi0 * cn2.y;
            s1.x = ff.x ? 1.0f : acc[nb2][2] * xi1 * cn2.x;
            s1.y = ff.y ? 1.0f : acc[nb2][3] * xi1 * cn2.y;
            if (r0g < B)     *(float2*)(o0 + c0) = s0;
            if (r0g + 8 < B) *(float2*)(o1 + c0) = s1;
        }

        dp ^= 1;
    }
}

extern "C" void kernel_launch(void* const* d_in, const int* in_sizes, int n_in,
                              void* d_out, int out_size) {
    const float* X = (const float*)d_in[0];   // inputs [B, 256] fp32
    // d_in[1] = labels (unused)
    const float* A = (const float*)d_in[2];   // class_avgs [64, 256] fp32
    float* out = (float*)d_out;

    int B = in_sizes[0] / 256;
    int ntiles = (B + 63) / 64;

    int dev = 0, nsm = 148;
    cudaGetDevice(&dev);
    cudaDeviceGetAttribute(&nsm, cudaDevAttrMultiProcessorCount, dev);
    if (nsm > ntiles) nsm = ntiles;

    cudaFuncSetAttribute(SimRel_48335561949951_kernel,
                         cudaFuncAttributeMaxDynamicSharedMemorySize, S_TOTAL);

    SimRel_48335561949951_kernel<<<nsm, THREADS, S_TOTAL>>>(X, A, out, B, ntiles);
}

// round 7
// speedup vs baseline: 3.3143x; 1.5396x over previous
#include <cuda_runtime.h>
#include <cstdint>
#include <math.h>

// SimRel via single-pass fp16 mma.sync (HMMA). R7: fp16 rn (2^-12) replaces
// bf16 3-pass split -> 1/3 the MMAs and ldsm traffic; expected rel_err ~1.5e-4
// (norms computed exactly in fp32). Tile M=64, double-buffered fp16 X smem,
// register prefetch, one __syncthreads per tile, 2 CTAs/SM (smem ~100KB).
// Warp (q=w>>2, h=w&3) computes M=32 rows x N=16 classes.
// B=262144, D=256, C=64.

#define THREADS 256
#define SROW    528                 // 264 fp16 per row (256 + 8 pad), bytes

// ---- smem layout (bytes) ----
#define S_A     0                   // [64 x 264] fp16 centroids     33792
#define S_X0    33792               // [64 x 264] fp16 X buf0        33792
#define S_X1    67584               // buf1                          33792
#define S_XINV  101376              // [2][64] f32 row rsqrt norms     512
#define S_CNI   101888              // [64] f32 centroid rsqrt norms   256
#define S_INF   102144              // [64] int inf flags              256
#define S_TOTAL 102400

__device__ __forceinline__ void sts64(uint32_t a, uint32_t x, uint32_t y) {
    asm volatile("st.shared.v2.b32 [%0], {%1,%2};" :: "r"(a), "r"(x), "r"(y));
}
__device__ __forceinline__ void ldsm4(uint32_t a, uint32_t& r0, uint32_t& r1,
                                      uint32_t& r2, uint32_t& r3) {
    asm volatile("ldmatrix.sync.aligned.m8n8.x4.shared.b16 {%0,%1,%2,%3}, [%4];"
                 : "=r"(r0), "=r"(r1), "=r"(r2), "=r"(r3) : "r"(a));
}
__device__ __forceinline__ void mma16816(float* c, uint32_t a0, uint32_t a1,
                                         uint32_t a2, uint32_t a3,
                                         uint32_t b0, uint32_t b1) {
    asm volatile("mma.sync.aligned.m16n8k16.row.col.f32.f16.f16.f32 "
                 "{%0,%1,%2,%3}, {%4,%5,%6,%7}, {%8,%9}, {%0,%1,%2,%3};"
                 : "+f"(c[0]), "+f"(c[1]), "+f"(c[2]), "+f"(c[3])
                 : "r"(a0), "r"(a1), "r"(a2), "r"(a3), "r"(b0), "r"(b1));
}

// float4 -> two packed f16x2 (rn): r0 = {lo=x, hi=y}, r1 = {lo=z, hi=w}
__device__ __forceinline__ void cvt_f16(float4 v, uint32_t& r0, uint32_t& r1) {
    asm("cvt.rn.f16x2.f32 %0, %1, %2;" : "=r"(r0) : "f"(v.y), "f"(v.x));
    asm("cvt.rn.f16x2.f32 %0, %1, %2;" : "=r"(r1) : "f"(v.w), "f"(v.z));
}

__device__ __forceinline__ float sum8(float4 a, float4 b) {
    float s = a.x * a.x;
    s = fmaf(a.y, a.y, s); s = fmaf(a.z, a.z, s); s = fmaf(a.w, a.w, s);
    s = fmaf(b.x, b.x, s); s = fmaf(b.y, b.y, s);
    s = fmaf(b.z, b.z, s); s = fmaf(b.w, b.w, s);
    return s;
}

__global__ void __launch_bounds__(THREADS, 2)
SimRel_48335561949951_kernel(const float* __restrict__ X,
                             const float* __restrict__ A,
                             float* __restrict__ out,
                             int B, int ntiles) {
    extern __shared__ char smem[];
    const uint32_t sb = (uint32_t)__cvta_generic_to_shared(smem);
    float* xinv_s = (float*)(smem + S_XINV);
    float* cni_s  = (float*)(smem + S_CNI);
    int*   inf_s  = (int*)(smem + S_INF);

    const int tid = threadIdx.x, w = tid >> 5, l = tid & 31;
    const int q = w >> 2;           // M-half: rows q*32..q*32+31
    const int h = w & 3;            // N-quarter: classes h*16..h*16+15

    // ---- centroid conversion + norms + inf flags (8 rows per warp, once) ----
    #pragma unroll
    for (int rr = 0; rr < 8; rr++) {
        int r = w * 8 + rr;
        const float4* pa = (const float4*)(A + (size_t)r * 256);
        float4 v0 = pa[l], v1 = pa[32 + l];
        uint32_t c0r, c1r;
        cvt_f16(v0, c0r, c1r);
        sts64(sb + S_A + r * SROW + 8 * l, c0r, c1r);
        cvt_f16(v1, c0r, c1r);
        sts64(sb + S_A + r * SROW + 256 + 8 * l, c0r, c1r);
        float ss = sum8(v0, v1);
        int bad = (fabsf(v0.x) == INFINITY) | (fabsf(v0.y) == INFINITY) |
                  (fabsf(v0.z) == INFINITY) | (fabsf(v0.w) == INFINITY) |
                  (fabsf(v1.x) == INFINITY) | (fabsf(v1.y) == INFINITY) |
                  (fabsf(v1.z) == INFINITY) | (fabsf(v1.w) == INFINITY);
        #pragma unroll
        for (int o = 16; o; o >>= 1) ss += __shfl_xor_sync(0xffffffffu, ss, o);
        unsigned m = __ballot_sync(0xffffffffu, bad);
        if (l == 0) { cni_s[r] = rsqrtf(ss); inf_s[r] = (m != 0); }
    }
    __syncthreads();

    // ---- per-lane ldmatrix fragment offsets ----
    const int t8 = l >> 3;
    const uint32_t frag_off = (uint32_t)(((t8 & 1) * 8 + (l & 7)) * SROW + (t8 >> 1) * 16);
    const uint32_t xfrag0 = (uint32_t)(q * 32) * SROW + frag_off;        // m-group 0
    const uint32_t xfrag1 = xfrag0 + 16 * SROW;                           // m-group 1
    const uint32_t afrag  = sb + S_A + (uint32_t)(h * 16) * SROW + frag_off;

    const int rbase = w * 8;        // 8 rows this warp loads/converts
    const int qr = l >> 2, qc = (l & 3) * 2;

    // ---- prologue: prefetch first tile's 8 rows into registers ----
    float4 va[8], vb[8];
    {
        long long tb = (long long)blockIdx.x * 64;
        #pragma unroll
        for (int rr = 0; rr < 8; rr++) {
            long long gr = tb + rbase + rr; if (gr >= B) gr = B - 1;
            const float4* px = (const float4*)(X + gr * 256);
            va[rr] = __ldcs(px + l);
            vb[rr] = __ldcs(px + 32 + l);
        }
    }

    int dp = 0;
    for (int tile = blockIdx.x; tile < ntiles; tile += gridDim.x) {
        const long long tb = (long long)tile * 64;
        const uint32_t xbuf = sb + (dp ? S_X1 : S_X0);

        // phase 1: convert prefetched rows -> fp16 smem + fp32 row norms
        {
            const uint32_t xsh = xbuf + (uint32_t)rbase * SROW;
            #pragma unroll
            for (int rr = 0; rr < 8; rr++) {
                uint32_t c0r, c1r;
                cvt_f16(va[rr], c0r, c1r);
                sts64(xsh + rr * SROW + 8 * l, c0r, c1r);
                cvt_f16(vb[rr], c0r, c1r);
                sts64(xsh + rr * SROW + 256 + 8 * l, c0r, c1r);
                float ss = sum8(va[rr], vb[rr]);
                #pragma unroll
                for (int o = 16; o; o >>= 1) ss += __shfl_xor_sync(0xffffffffu, ss, o);
                if (l == 0) xinv_s[dp * 64 + rbase + rr] = rsqrtf(ss);
            }
        }
        __syncthreads();   // buf dp fully written; everyone done with MMA(t-1)

        // phase 2a: issue next tile's LDGs (latency covered by MMA below)
        int nt = tile + gridDim.x;
        if (nt < ntiles) {
            long long nb = (long long)nt * 64;
            #pragma unroll
            for (int rr = 0; rr < 8; rr++) {
                long long gr = nb + rbase + rr; if (gr >= B) gr = B - 1;
                const float4* px = (const float4*)(X + gr * 256);
                va[rr] = __ldcs(px + l);
                vb[rr] = __ldcs(px + 32 + l);
            }
        }

        // phase 2b: single fp16 pass, 16 k-steps; M=32, N=16 per warp
        float acc[2][2][4];
        #pragma unroll
        for (int m = 0; m < 2; m++)
            #pragma unroll
            for (int n = 0; n < 2; n++)
                #pragma unroll
                for (int j = 0; j < 4; j++) acc[m][n][j] = 0.0f;

        #pragma unroll
        for (int s = 0; s < 16; s++) {
            uint32_t x0[4], x1[4], b0, b1, b2, b3;
            ldsm4(xbuf + xfrag0 + s * 32, x0[0], x0[1], x0[2], x0[3]);
            ldsm4(xbuf + xfrag1 + s * 32, x1[0], x1[1], x1[2], x1[3]);
            ldsm4(afrag + s * 32, b0, b1, b2, b3);
            mma16816(acc[0][0], x0[0], x0[1], x0[2], x0[3], b0, b2);
            mma16816(acc[0][1], x0[0], x0[1], x0[2], x0[3], b1, b3);
            mma16816(acc[1][0], x1[0], x1[1], x1[2], x1[3], b0, b2);
            mma16816(acc[1][1], x1[0], x1[1], x1[2], x1[3], b1, b3);
        }

        // phase 3: epilogue — scale + store (32 rows x 16 classes per warp)
        #pragma unroll
        for (int m = 0; m < 2; m++) {
            int rloc = q * 32 + m * 16 + qr;
            float xi0 = xinv_s[dp * 64 + rloc];
            float xi1 = xinv_s[dp * 64 + rloc + 8];
            long long r0g = tb + rloc;
            float* o0 = out + r0g * 64;
            float* o1 = o0 + 8 * 64;
            #pragma unroll
            for (int n = 0; n < 2; n++) {
                int c0 = h * 16 + n * 8 + qc;
                float2 cn2 = *(const float2*)(cni_s + c0);
                int2   ff  = *(const int2*)(inf_s + c0);
                float2 s0, s1;
                s0.x = ff.x ? 1.0f : acc[m][n][0] * xi0 * cn2.x;
                s0.y = ff.y ? 1.0f : acc[m][n][1] * xi0 * cn2.y;
                s1.x = ff.x ? 1.0f : acc[m][n][2] * xi1 * cn2.x;
                s1.y = ff.y ? 1.0f : acc[m][n][3] * xi1 * cn2.y;
                if (r0g < B)     *(float2*)(o0 + c0) = s0;
                if (r0g + 8 < B) *(float2*)(o1 + c0) = s1;
            }
        }

        dp ^= 1;
    }
}

extern "C" void kernel_launch(void* const* d_in, const int* in_sizes, int n_in,
                              void* d_out, int out_size) {
    const float* X = (const float*)d_in[0];   // inputs [B, 256] fp32
    // d_in[1] = labels (unused)
    const float* A = (const float*)d_in[2];   // class_avgs [64, 256] fp32
    float* out = (float*)d_out;

    int B = in_sizes[0] / 256;
    int ntiles = (B + 63) / 64;

    int dev = 0, nsm = 148;
    cudaGetDevice(&dev);
    cudaDeviceGetAttribute(&nsm, cudaDevAttrMultiProcessorCount, dev);

    int grid = 2 * nsm;             // 2 CTAs/SM (smem 100KB, regs <=128)
    if (grid > ntiles) grid = ntiles;

    cudaFuncSetAttribute(SimRel_48335561949951_kernel,
                         cudaFuncAttributeMaxDynamicSharedMemorySize, S_TOTAL);

    SimRel_48335561949951_kernel<<<grid, THREADS, S_TOTAL>>>(X, A, out, B, ntiles);
}

// round 8
// speedup vs baseline: 3.3947x; 1.0242x over previous
#include <cuda_runtime.h>
#include <cstdint>
#include <math.h>

// SimRel via single-pass fp16 mma.sync. R8: tile M=128, warp tiles 32x32
// (ldsm/MMA ratio 0.5 vs R7's 0.75), single fp16 X smem buffer, 2 CTAs/SM,
// software-pipelined 8-row LDG waves inside the convert loop, streaming STG.
// out = dot * rsqrt(|x|^2) * rsqrt(|a|^2) (norms exact fp32); 1.0 on inf rows.
// B=262144, D=256, C=64.

#define THREADS 256
#define SROW    528                 // 264 fp16 per row (256 + 8 pad), bytes

// ---- smem layout (bytes) ----
#define S_A     0                   // [64 x 264] fp16 centroids     33792
#define S_X     33792               // [128 x 264] fp16 X tile       67584
#define S_XINV  101376              // [128] f32 row rsqrt norms       512
#define S_CNI   101888              // [64] f32 centroid rsqrt norms   256
#define S_INF   102144              // [64] int inf flags              256
#define S_TOTAL 102400

__device__ __forceinline__ void sts64(uint32_t a, uint32_t x, uint32_t y) {
    asm volatile("st.shared.v2.b32 [%0], {%1,%2};" :: "r"(a), "r"(x), "r"(y));
}
__device__ __forceinline__ void ldsm4(uint32_t a, uint32_t& r0, uint32_t& r1,
                                      uint32_t& r2, uint32_t& r3) {
    asm volatile("ldmatrix.sync.aligned.m8n8.x4.shared.b16 {%0,%1,%2,%3}, [%4];"
                 : "=r"(r0), "=r"(r1), "=r"(r2), "=r"(r3) : "r"(a));
}
__device__ __forceinline__ void mma16816(float* c, uint32_t a0, uint32_t a1,
                                         uint32_t a2, uint32_t a3,
                                         uint32_t b0, uint32_t b1) {
    asm volatile("mma.sync.aligned.m16n8k16.row.col.f32.f16.f16.f32 "
                 "{%0,%1,%2,%3}, {%4,%5,%6,%7}, {%8,%9}, {%0,%1,%2,%3};"
                 : "+f"(c[0]), "+f"(c[1]), "+f"(c[2]), "+f"(c[3])
                 : "r"(a0), "r"(a1), "r"(a2), "r"(a3), "r"(b0), "r"(b1));
}
__device__ __forceinline__ void cvt_f16(float4 v, uint32_t& r0, uint32_t& r1) {
    asm("cvt.rn.f16x2.f32 %0, %1, %2;" : "=r"(r0) : "f"(v.y), "f"(v.x));
    asm("cvt.rn.f16x2.f32 %0, %1, %2;" : "=r"(r1) : "f"(v.w), "f"(v.z));
}
__device__ __forceinline__ void stg_cs64(float* p, float2 v) {
    asm volatile("st.global.cs.v2.f32 [%0], {%1,%2};" :: "l"(p), "f"(v.x), "f"(v.y));
}
__device__ __forceinline__ float sum8(float4 a, float4 b) {
    float s = a.x * a.x;
    s = fmaf(a.y, a.y, s); s = fmaf(a.z, a.z, s); s = fmaf(a.w, a.w, s);
    s = fmaf(b.x, b.x, s); s = fmaf(b.y, b.y, s);
    s = fmaf(b.z, b.z, s); s = fmaf(b.w, b.w, s);
    return s;
}

__global__ void __launch_bounds__(THREADS, 2)
SimRel_48335561949951_kernel(const float* __restrict__ X,
                             const float* __restrict__ A,
                             float* __restrict__ out,
                             int B, int ntiles) {
    extern __shared__ char smem[];
    const uint32_t sb = (uint32_t)__cvta_generic_to_shared(smem);
    float* xinv_s = (float*)(smem + S_XINV);
    float* cni_s  = (float*)(smem + S_CNI);
    int*   inf_s  = (int*)(smem + S_INF);

    const int tid = threadIdx.x, w = tid >> 5, l = tid & 31;
    const int q = w >> 1;           // M-slot: rows q*32..q*32+31
    const int h = w & 1;            // N-slot: classes h*32..h*32+31

    // ---- centroid conversion + norms + inf flags (8 rows per warp, once) ----
    #pragma unroll
    for (int rr = 0; rr < 8; rr++) {
        int r = w * 8 + rr;
        const float4* pa = (const float4*)(A + (size_t)r * 256);
        float4 v0 = pa[l], v1 = pa[32 + l];
        uint32_t c0r, c1r;
        cvt_f16(v0, c0r, c1r);
        sts64(sb + S_A + r * SROW + 8 * l, c0r, c1r);
        cvt_f16(v1, c0r, c1r);
        sts64(sb + S_A + r * SROW + 256 + 8 * l, c0r, c1r);
        float ss = sum8(v0, v1);
        int bad = (fabsf(v0.x) == INFINITY) | (fabsf(v0.y) == INFINITY) |
                  (fabsf(v0.z) == INFINITY) | (fabsf(v0.w) == INFINITY) |
                  (fabsf(v1.x) == INFINITY) | (fabsf(v1.y) == INFINITY) |
                  (fabsf(v1.z) == INFINITY) | (fabsf(v1.w) == INFINITY);
        #pragma unroll
        for (int o = 16; o; o >>= 1) ss += __shfl_xor_sync(0xffffffffu, ss, o);
        unsigned m = __ballot_sync(0xffffffffu, bad);
        if (l == 0) { cni_s[r] = rsqrtf(ss); inf_s[r] = (m != 0); }
    }
    __syncthreads();

    // ---- per-lane ldmatrix fragment offsets ----
    const int t8 = l >> 3;
    const uint32_t frag_off = (uint32_t)(((t8 & 1) * 8 + (l & 7)) * SROW + (t8 >> 1) * 16);
    const uint32_t xf0 = sb + S_X + (uint32_t)(q * 32) * SROW + frag_off;   // m-group 0
    const uint32_t xf1 = xf0 + 16 * SROW;                                    // m-group 1
    const uint32_t af0 = sb + S_A + (uint32_t)(h * 32) * SROW + frag_off;   // n-blocks 0,1
    const uint32_t af1 = af0 + 16 * SROW;                                    // n-blocks 2,3

    const int rbase = w * 16;       // 16 rows this warp converts (2 waves of 8)
    const int qr = l >> 2, qc = (l & 3) * 2;

    // ---- prologue: LDG wave0 of first tile ----
    float4 va[8], vb[8];
    {
        long long tb = (long long)blockIdx.x * 128;
        #pragma unroll
        for (int rr = 0; rr < 8; rr++) {
            long long gr = tb + rbase + rr; if (gr >= B) gr = B - 1;
            const float4* px = (const float4*)(X + gr * 256);
            va[rr] = __ldcs(px + l);
            vb[rr] = __ldcs(px + 32 + l);
        }
    }

    for (int tile = blockIdx.x; tile < ntiles; tile += gridDim.x) {
        const long long tb = (long long)tile * 128;
        const int nt = tile + gridDim.x;
        const long long nb = (long long)nt * 128;

        // phase 1a: convert wave0 (regs) -> smem, and pipeline wave1 LDGs in
        {
            const uint32_t xsh = sb + S_X + (uint32_t)rbase * SROW;
            #pragma unroll
            for (int rr = 0; rr < 8; rr++) {
                uint32_t c0r, c1r;
                cvt_f16(va[rr], c0r, c1r);
                sts64(xsh + rr * SROW + 8 * l, c0r, c1r);
                cvt_f16(vb[rr], c0r, c1r);
                sts64(xsh + rr * SROW + 256 + 8 * l, c0r, c1r);
                float ss = sum8(va[rr], vb[rr]);
                #pragma unroll
                for (int o = 16; o; o >>= 1) ss += __shfl_xor_sync(0xffffffffu, ss, o);
                if (l == 0) xinv_s[rbase + rr] = rsqrtf(ss);
                // refill with wave1 row rr of THIS tile
                long long gr = tb + rbase + 8 + rr; if (gr >= B) gr = B - 1;
                const float4* px = (const float4*)(X + gr * 256);
                va[rr] = __ldcs(px + l);
                vb[rr] = __ldcs(px + 32 + l);
            }
        }
        // phase 1b: convert wave1, pipeline next tile's wave0 LDGs in
        {
            const uint32_t xsh = sb + S_X + (uint32_t)(rbase + 8) * SROW;
            #pragma unroll
            for (int rr = 0; rr < 8; rr++) {
                uint32_t c0r, c1r;
                cvt_f16(va[rr], c0r, c1r);
                sts64(xsh + rr * SROW + 8 * l, c0r, c1r);
                cvt_f16(vb[rr], c0r, c1r);
                sts64(xsh + rr * SROW + 256 + 8 * l, c0r, c1r);
                float ss = sum8(va[rr], vb[rr]);
                #pragma unroll
                for (int o = 16; o; o >>= 1) ss += __shfl_xor_sync(0xffffffffu, ss, o);
                if (l == 0) xinv_s[rbase + 8 + rr] = rsqrtf(ss);
                if (nt < ntiles) {
                    long long gr = nb + rbase + rr; if (gr >= B) gr = B - 1;
                    const float4* px = (const float4*)(X + gr * 256);
                    va[rr] = __ldcs(px + l);
                    vb[rr] = __ldcs(px + 32 + l);
                }
            }
        }
        __syncthreads();   // X tile + norms complete

        // phase 2: 16 k-steps; warp computes 32 rows x 32 classes
        float acc[2][4][4];
        #pragma unroll
        for (int m = 0; m < 2; m++)
            #pragma unroll
            for (int n = 0; n < 4; n++)
                #pragma unroll
                for (int j = 0; j < 4; j++) acc[m][n][j] = 0.0f;

        #pragma unroll
        for (int s = 0; s < 16; s++) {
            uint32_t x0[4], x1[4], b0[4], b1[4];
            ldsm4(xf0 + s * 32, x0[0], x0[1], x0[2], x0[3]);
            ldsm4(xf1 + s * 32, x1[0], x1[1], x1[2], x1[3]);
            ldsm4(af0 + s * 32, b0[0], b0[1], b0[2], b0[3]);
            ldsm4(af1 + s * 32, b1[0], b1[1], b1[2], b1[3]);
            mma16816(acc[0][0], x0[0], x0[1], x0[2], x0[3], b0[0], b0[2]);
            mma16816(acc[0][1], x0[0], x0[1], x0[2], x0[3], b0[1], b0[3]);
            mma16816(acc[0][2], x0[0], x0[1], x0[2], x0[3], b1[0], b1[2]);
            mma16816(acc[0][3], x0[0], x0[1], x0[2], x0[3], b1[1], b1[3]);
            mma16816(acc[1][0], x1[0], x1[1], x1[2], x1[3], b0[0], b0[2]);
            mma16816(acc[1][1], x1[0], x1[1], x1[2], x1[3], b0[1], b0[3]);
            mma16816(acc[1][2], x1[0], x1[1], x1[2], x1[3], b1[0], b1[2]);
            mma16816(acc[1][3], x1[0], x1[1], x1[2], x1[3], b1[1], b1[3]);
        }

        // phase 3: epilogue — scale + streaming store (32 rows x 32 classes)
        #pragma unroll
        for (int m = 0; m < 2; m++) {
            int rloc = q * 32 + m * 16 + qr;
            float xi0 = xinv_s[rloc];
            float xi1 = xinv_s[rloc + 8];
            long long r0g = tb + rloc;
            float* o0 = out + r0g * 64;
            float* o1 = o0 + 8 * 64;
            #pragma unroll
            for (int n = 0; n < 4; n++) {
                int c0 = h * 32 + n * 8 + qc;
                float2 cn2 = *(const float2*)(cni_s + c0);
                int2   ff  = *(const int2*)(inf_s + c0);
                float2 s0, s1;
                s0.x = ff.x ? 1.0f : acc[m][n][0] * xi0 * cn2.x;
                s0.y = ff.y ? 1.0f : acc[m][n][1] * xi0 * cn2.y;
                s1.x = ff.x ? 1.0f : acc[m][n][2] * xi1 * cn2.x;
                s1.y = ff.y ? 1.0f : acc[m][n][3] * xi1 * cn2.y;
                if (r0g < B)     stg_cs64(o0 + c0, s0);
                if (r0g + 8 < B) stg_cs64(o1 + c0, s1);
            }
        }
        __syncthreads();   // all ldsm reads done before next tile's STS (WAR)
    }
}

extern "C" void kernel_launch(void* const* d_in, const int* in_sizes, int n_in,
                              void* d_out, int out_size) {
    const float* X = (const float*)d_in[0];   // inputs [B, 256] fp32
    // d_in[1] = labels (unused)
    const float* A = (const float*)d_in[2];   // class_avgs [64, 256] fp32
    float* out = (float*)d_out;

    int B = in_sizes[0] / 256;
    int ntiles = (B + 127) / 128;

    int dev = 0, nsm = 148;
    cudaGetDevice(&dev);
    cudaDeviceGetAttribute(&nsm, cudaDevAttrMultiProcessorCount, dev);

    int grid = 2 * nsm;             // 2 CTAs/SM
    if (grid > ntiles) grid = ntiles;

    cudaFuncSetAttribute(SimRel_48335561949951_kernel,
                         cudaFuncAttributeMaxDynamicSharedMemorySize, S_TOTAL);

    SimRel_48335561949951_kernel<<<grid, THREADS, S_TOTAL>>>(X, A, out, B, ntiles);
}